// round 1
// baseline (speedup 1.0000x reference)
#include <cuda_runtime.h>
#include <math.h>

#define BSZ  4
#define HN   16
#define LSEQ 2048
#define DM   1024
#define DH   64

// -------- scratch (device globals: allocation-free per harness rules) --------
__device__ float g_q[(long long)BSZ * HN * LSEQ * DH];        // 32 MB
__device__ float g_k[(long long)BSZ * HN * LSEQ * DH];        // 32 MB
__device__ float g_v[(long long)BSZ * HN * LSEQ * DH];        // 32 MB
__device__ float g_attn[(long long)BSZ * HN * LSEQ * LSEQ];   // 1 GiB
__device__ float g_outs[(long long)BSZ * LSEQ * DM];          // 32 MB (fallback)

// ---------------------------------------------------------------------------
// Projection: Y = X @ W^T, X:[M=B*L, D], W:[D, D] row-major (out_feat x in_feat)
// Output scattered into head-major layout [B, H, L, dh].
// 64x64 tile per block, 16x16 threads, 4x4 per thread, K-tiles of 16.
// ---------------------------------------------------------------------------
__global__ void proj_kernel(const float* __restrict__ X,
                            const float* __restrict__ W,
                            float* __restrict__ Y) {
    __shared__ float As[64][17];
    __shared__ float Ws[64][17];
    const int bm = blockIdx.y * 64;
    const int bn = blockIdx.x * 64;
    const int tid = threadIdx.y * 16 + threadIdx.x;
    const int tm = threadIdx.y * 4;
    const int tn = threadIdx.x * 4;

    float acc[4][4] = {};

    for (int k0 = 0; k0 < DM; k0 += 16) {
#pragma unroll
        for (int i = 0; i < 4; i++) {
            int idx = tid + i * 256;
            int r = idx >> 4;
            int c = idx & 15;
            As[r][c] = X[(size_t)(bm + r) * DM + k0 + c];
            Ws[r][c] = W[(size_t)(bn + r) * DM + k0 + c];
        }
        __syncthreads();
#pragma unroll
        for (int k = 0; k < 16; k++) {
            float a0 = As[tm + 0][k], a1 = As[tm + 1][k];
            float a2 = As[tm + 2][k], a3 = As[tm + 3][k];
            float b0 = Ws[tn + 0][k], b1 = Ws[tn + 1][k];
            float b2 = Ws[tn + 2][k], b3 = Ws[tn + 3][k];
            acc[0][0] += a0 * b0; acc[0][1] += a0 * b1; acc[0][2] += a0 * b2; acc[0][3] += a0 * b3;
            acc[1][0] += a1 * b0; acc[1][1] += a1 * b1; acc[1][2] += a1 * b2; acc[1][3] += a1 * b3;
            acc[2][0] += a2 * b0; acc[2][1] += a2 * b1; acc[2][2] += a2 * b2; acc[2][3] += a2 * b3;
            acc[3][0] += a3 * b0; acc[3][1] += a3 * b1; acc[3][2] += a3 * b2; acc[3][3] += a3 * b3;
        }
        __syncthreads();
    }

#pragma unroll
    for (int i = 0; i < 4; i++) {
        int m = bm + tm + i;
        int b = m >> 11;          // L = 2048
        int l = m & 2047;
#pragma unroll
        for (int j = 0; j < 4; j++) {
            int n = bn + tn + j;
            int h = n >> 6;       // dh = 64
            int dd = n & 63;
            Y[(((size_t)(b * HN + h)) * LSEQ + l) * DH + dd] = acc[i][j];
        }
    }
}

// ---------------------------------------------------------------------------
// Fused attention: block = (b,h) x 32 q-rows, 256 threads (8 warps).
// Warp w owns rows w*4..w*4+3; lane owns 2 columns (S) / 2 d-channels (O).
// Phase 1: S = QK^T/8, store raw S to attn buffer, row-max in registers.
// Phase 2: re-read S (L2 hot), compute exp-sum.
// Phase 3: re-read S, write normalized P, accumulate O = P @ V from smem.
// ---------------------------------------------------------------------------
__global__ void attn_kernel(float* __restrict__ attn, float* __restrict__ out) {
    __shared__ float Qs[32][DH + 1];
    __shared__ float KVs[64][DH + 1];
    __shared__ float Ss[32][DH + 1];

    const int bh = blockIdx.y;            // b*HN + h
    const int q0 = blockIdx.x * 32;
    const int tid = threadIdx.x;
    const int w = tid >> 5;
    const int lane = tid & 31;

    const float* qp = g_q + ((size_t)bh * LSEQ + q0) * DH;
    const float* kp = g_k + (size_t)bh * LSEQ * DH;
    const float* vp = g_v + (size_t)bh * LSEQ * DH;
    float* ap = attn + ((size_t)bh * LSEQ + q0) * LSEQ;

    // Load Q tile [32][64]
    for (int i = tid; i < 32 * DH; i += 256)
        Qs[i >> 6][i & 63] = qp[i];
    __syncthreads();

    float pmax[4];
#pragma unroll
    for (int i = 0; i < 4; i++) pmax[i] = -1e30f;

    // ---- Phase 1: scores + raw store + running max ----
    for (int kt = 0; kt < LSEQ / 64; kt++) {
        const float* kk = kp + (size_t)kt * 64 * DH;
        for (int i = tid; i < 64 * DH; i += 256)
            KVs[i >> 6][i & 63] = kk[i];
        __syncthreads();

        float s[4][2] = {};
#pragma unroll
        for (int d = 0; d < DH; d++) {
            float k0v = KVs[2 * lane][d];
            float k1v = KVs[2 * lane + 1][d];
#pragma unroll
            for (int i = 0; i < 4; i++) {
                float qv = Qs[w * 4 + i][d];
                s[i][0] += qv * k0v;
                s[i][1] += qv * k1v;
            }
        }
#pragma unroll
        for (int i = 0; i < 4; i++) {
            s[i][0] *= 0.125f;  // 1/sqrt(64)
            s[i][1] *= 0.125f;
            pmax[i] = fmaxf(pmax[i], fmaxf(s[i][0], s[i][1]));
            *(float2*)&ap[(size_t)(w * 4 + i) * LSEQ + kt * 64 + 2 * lane] =
                make_float2(s[i][0], s[i][1]);
        }
        __syncthreads();
    }

    // Row-max: warp-level reduce (each warp owns its 4 rows entirely)
#pragma unroll
    for (int i = 0; i < 4; i++) {
        float m = pmax[i];
#pragma unroll
        for (int off = 16; off; off >>= 1)
            m = fmaxf(m, __shfl_xor_sync(0xFFFFFFFFu, m, off));
        pmax[i] = m;
    }

    // ---- Phase 2: exp-sum ----
    float psum[4] = {0.f, 0.f, 0.f, 0.f};
    for (int kt = 0; kt < LSEQ / 64; kt++) {
#pragma unroll
        for (int i = 0; i < 4; i++) {
            float2 v2 = *(const float2*)&ap[(size_t)(w * 4 + i) * LSEQ + kt * 64 + 2 * lane];
            psum[i] += __expf(v2.x - pmax[i]) + __expf(v2.y - pmax[i]);
        }
    }
#pragma unroll
    for (int i = 0; i < 4; i++) {
        float sgl = psum[i];
#pragma unroll
        for (int off = 16; off; off >>= 1)
            sgl += __shfl_xor_sync(0xFFFFFFFFu, sgl, off);
        psum[i] = 1.0f / sgl;   // inverse sum, identical in all lanes
    }

    // ---- Phase 3: normalized P store + O = P @ V ----
    float o[4][2] = {};
    for (int kt = 0; kt < LSEQ / 64; kt++) {
        const float* vv = vp + (size_t)kt * 64 * DH;
        for (int i = tid; i < 64 * DH; i += 256)
            KVs[i >> 6][i & 63] = vv[i];

#pragma unroll
        for (int i = 0; i < 4; i++) {
            size_t off = (size_t)(w * 4 + i) * LSEQ + kt * 64 + 2 * lane;
            float2 v2 = *(const float2*)&ap[off];
            float p0 = __expf(v2.x - pmax[i]) * psum[i];
            float p1 = __expf(v2.y - pmax[i]) * psum[i];
            *(float2*)&ap[off] = make_float2(p0, p1);
            Ss[w * 4 + i][2 * lane] = p0;
            Ss[w * 4 + i][2 * lane + 1] = p1;
        }
        __syncthreads();

#pragma unroll
        for (int k = 0; k < 64; k++) {
            float v0 = KVs[k][2 * lane];
            float v1 = KVs[k][2 * lane + 1];
#pragma unroll
            for (int i = 0; i < 4; i++) {
                float pv = Ss[w * 4 + i][k];
                o[i][0] += pv * v0;
                o[i][1] += pv * v1;
            }
        }
        __syncthreads();
    }

    // Write O: out[b][q][h*64 + d]
    const int b = bh >> 4;     // HN = 16
    const int h = bh & 15;
#pragma unroll
    for (int i = 0; i < 4; i++) {
        size_t off = ((size_t)b * LSEQ + q0 + w * 4 + i) * DM + h * DH + 2 * lane;
        *(float2*)&out[off] = make_float2(o[i][0], o[i][1]);
    }
}

// ---------------------------------------------------------------------------
extern "C" void kernel_launch(void* const* d_in, const int* in_sizes, int n_in,
                              void* d_out, int out_size) {
    const float* q_in = (const float*)d_in[0];
    const float* k_in = (const float*)d_in[1];
    const float* v_in = (const float*)d_in[2];
    const float* wq   = (const float*)d_in[3];
    const float* wk   = (const float*)d_in[4];
    const float* wv   = (const float*)d_in[5];

    float *qb, *kb, *vb, *attn_scratch, *out_scratch;
    cudaGetSymbolAddress((void**)&qb, g_q);
    cudaGetSymbolAddress((void**)&kb, g_k);
    cudaGetSymbolAddress((void**)&vb, g_v);
    cudaGetSymbolAddress((void**)&attn_scratch, g_attn);
    cudaGetSymbolAddress((void**)&out_scratch, g_outs);

    const long long out_elems  = (long long)BSZ * LSEQ * DM;          // 8388608
    const long long attn_elems = (long long)BSZ * HN * LSEQ * LSEQ;   // 268435456

    float* out_ptr  = (float*)d_out;
    float* attn_ptr = attn_scratch;
    long long osz = (long long)out_size;
    if (osz >= out_elems + attn_elems) {
        attn_ptr = (float*)d_out + out_elems;          // output = (out, attn)
    } else if (osz == attn_elems) {
        attn_ptr = (float*)d_out;                       // output = attn only
        out_ptr  = out_scratch;
    }                                                   // else: out only

    dim3 pgrid(DM / 64, (BSZ * LSEQ) / 64);
    dim3 pblk(16, 16);
    proj_kernel<<<pgrid, pblk>>>(q_in, wq, qb);
    proj_kernel<<<pgrid, pblk>>>(k_in, wk, kb);
    proj_kernel<<<pgrid, pblk>>>(v_in, wv, vb);

    dim3 agrid(LSEQ / 32, BSZ * HN);
    attn_kernel<<<agrid, 256>>>(attn_ptr, out_ptr);
}

// round 3
// speedup vs baseline: 1.0531x; 1.0531x over previous
#include <cuda_runtime.h>
#include <math.h>

#define BSZ  4
#define HN   16
#define LSEQ 2048
#define DM   1024
#define DH   64

// -------- scratch (device globals: allocation-free per harness rules) --------
__device__ float g_q[(long long)BSZ * HN * LSEQ * DH];        // 32 MB
__device__ float g_k[(long long)BSZ * HN * LSEQ * DH];        // 32 MB
__device__ float g_v[(long long)BSZ * HN * LSEQ * DH];        // 32 MB
__device__ float g_attn[(long long)BSZ * HN * LSEQ * LSEQ];   // 1 GiB
__device__ float g_outs[(long long)BSZ * LSEQ * DM];          // 32 MB (fallback)

// ---------------------------------------------------------------------------
// Projection: Y = X @ W^T, X:[M=B*L, D], W:[D, D] row-major (out_feat x in_feat)
// Output scattered into head-major layout [B, H, L, dh].
// 64x64 tile per block, 16x16 threads, 4x4 per thread, K-tiles of 16.
// ---------------------------------------------------------------------------
__global__ void proj_kernel(const float* __restrict__ X,
                            const float* __restrict__ W,
                            float* __restrict__ Y) {
    __shared__ float As[64][17];
    __shared__ float Ws[64][17];
    const int bm = blockIdx.y * 64;
    const int bn = blockIdx.x * 64;
    const int tid = threadIdx.y * 16 + threadIdx.x;
    const int tm = threadIdx.y * 4;
    const int tn = threadIdx.x * 4;

    float acc[4][4] = {};

    for (int k0 = 0; k0 < DM; k0 += 16) {
#pragma unroll
        for (int i = 0; i < 4; i++) {
            int idx = tid + i * 256;
            int r = idx >> 4;
            int c = idx & 15;
            As[r][c] = X[(size_t)(bm + r) * DM + k0 + c];
            Ws[r][c] = W[(size_t)(bn + r) * DM + k0 + c];
        }
        __syncthreads();
#pragma unroll
        for (int k = 0; k < 16; k++) {
            float a0 = As[tm + 0][k], a1 = As[tm + 1][k];
            float a2 = As[tm + 2][k], a3 = As[tm + 3][k];
            float b0 = Ws[tn + 0][k], b1 = Ws[tn + 1][k];
            float b2 = Ws[tn + 2][k], b3 = Ws[tn + 3][k];
            acc[0][0] += a0 * b0; acc[0][1] += a0 * b1; acc[0][2] += a0 * b2; acc[0][3] += a0 * b3;
            acc[1][0] += a1 * b0; acc[1][1] += a1 * b1; acc[1][2] += a1 * b2; acc[1][3] += a1 * b3;
            acc[2][0] += a2 * b0; acc[2][1] += a2 * b1; acc[2][2] += a2 * b2; acc[2][3] += a2 * b3;
            acc[3][0] += a3 * b0; acc[3][1] += a3 * b1; acc[3][2] += a3 * b2; acc[3][3] += a3 * b3;
        }
        __syncthreads();
    }

#pragma unroll
    for (int i = 0; i < 4; i++) {
        int m = bm + tm + i;
        int b = m >> 11;          // L = 2048
        int l = m & 2047;
#pragma unroll
        for (int j = 0; j < 4; j++) {
            int n = bn + tn + j;
            int h = n >> 6;       // dh = 64
            int dd = n & 63;
            Y[(((size_t)(b * HN + h)) * LSEQ + l) * DH + dd] = acc[i][j];
        }
    }
}

// ---------------------------------------------------------------------------
// Fused attention: block = (b,h) x 32 q-rows, 256 threads (8 warps).
// Warp w owns rows w*4..w*4+3; lane owns 2 columns (S) / 2 d-channels (O).
// Phase 1: S = QK^T/8, store raw S to attn buffer, row-max in registers.
// Phase 2: re-read S (L2 hot), compute exp-sum.
// Phase 3: re-read S, write normalized P, accumulate O = P @ V from smem.
// ---------------------------------------------------------------------------
__global__ void attn_kernel(float* __restrict__ attn, float* __restrict__ out) {
    __shared__ float Qs[32][DH + 1];
    __shared__ float KVs[64][DH + 1];
    __shared__ float Ss[32][DH + 1];

    const int bh = blockIdx.y;            // b*HN + h
    const int q0 = blockIdx.x * 32;
    const int tid = threadIdx.x;
    const int w = tid >> 5;
    const int lane = tid & 31;

    const float* qp = g_q + ((size_t)bh * LSEQ + q0) * DH;
    const float* kp = g_k + (size_t)bh * LSEQ * DH;
    const float* vp = g_v + (size_t)bh * LSEQ * DH;
    float* ap = attn + ((size_t)bh * LSEQ + q0) * LSEQ;

    // Load Q tile [32][64]
    for (int i = tid; i < 32 * DH; i += 256)
        Qs[i >> 6][i & 63] = qp[i];
    __syncthreads();

    float pmax[4];
#pragma unroll
    for (int i = 0; i < 4; i++) pmax[i] = -1e30f;

    // ---- Phase 1: scores + raw store + running max ----
    for (int kt = 0; kt < LSEQ / 64; kt++) {
        const float* kk = kp + (size_t)kt * 64 * DH;
        for (int i = tid; i < 64 * DH; i += 256)
            KVs[i >> 6][i & 63] = kk[i];
        __syncthreads();

        float s[4][2] = {};
#pragma unroll
        for (int d = 0; d < DH; d++) {
            float k0v = KVs[2 * lane][d];
            float k1v = KVs[2 * lane + 1][d];
#pragma unroll
            for (int i = 0; i < 4; i++) {
                float qv = Qs[w * 4 + i][d];
                s[i][0] += qv * k0v;
                s[i][1] += qv * k1v;
            }
        }
#pragma unroll
        for (int i = 0; i < 4; i++) {
            s[i][0] *= 0.125f;  // 1/sqrt(64)
            s[i][1] *= 0.125f;
            pmax[i] = fmaxf(pmax[i], fmaxf(s[i][0], s[i][1]));
            *(float2*)&ap[(size_t)(w * 4 + i) * LSEQ + kt * 64 + 2 * lane] =
                make_float2(s[i][0], s[i][1]);
        }
        __syncthreads();
    }

    // Row-max: warp-level reduce (each warp owns its 4 rows entirely)
#pragma unroll
    for (int i = 0; i < 4; i++) {
        float m = pmax[i];
#pragma unroll
        for (int off = 16; off; off >>= 1)
            m = fmaxf(m, __shfl_xor_sync(0xFFFFFFFFu, m, off));
        pmax[i] = m;
    }

    // ---- Phase 2: exp-sum ----
    float psum[4] = {0.f, 0.f, 0.f, 0.f};
    for (int kt = 0; kt < LSEQ / 64; kt++) {
#pragma unroll
        for (int i = 0; i < 4; i++) {
            float2 v2 = *(const float2*)&ap[(size_t)(w * 4 + i) * LSEQ + kt * 64 + 2 * lane];
            psum[i] += __expf(v2.x - pmax[i]) + __expf(v2.y - pmax[i]);
        }
    }
#pragma unroll
    for (int i = 0; i < 4; i++) {
        float sgl = psum[i];
#pragma unroll
        for (int off = 16; off; off >>= 1)
            sgl += __shfl_xor_sync(0xFFFFFFFFu, sgl, off);
        psum[i] = 1.0f / sgl;   // inverse sum, identical in all lanes
    }

    // ---- Phase 3: normalized P store + O = P @ V ----
    float o[4][2] = {};
    for (int kt = 0; kt < LSEQ / 64; kt++) {
        const float* vv = vp + (size_t)kt * 64 * DH;
        for (int i = tid; i < 64 * DH; i += 256)
            KVs[i >> 6][i & 63] = vv[i];

#pragma unroll
        for (int i = 0; i < 4; i++) {
            size_t off = (size_t)(w * 4 + i) * LSEQ + kt * 64 + 2 * lane;
            float2 v2 = *(const float2*)&ap[off];
            float p0 = __expf(v2.x - pmax[i]) * psum[i];
            float p1 = __expf(v2.y - pmax[i]) * psum[i];
            *(float2*)&ap[off] = make_float2(p0, p1);
            Ss[w * 4 + i][2 * lane] = p0;
            Ss[w * 4 + i][2 * lane + 1] = p1;
        }
        __syncthreads();

#pragma unroll
        for (int k = 0; k < 64; k++) {
            float v0 = KVs[k][2 * lane];
            float v1 = KVs[k][2 * lane + 1];
#pragma unroll
            for (int i = 0; i < 4; i++) {
                float pv = Ss[w * 4 + i][k];
                o[i][0] += pv * v0;
                o[i][1] += pv * v1;
            }
        }
        __syncthreads();
    }

    // Write O: out[b][q][h*64 + d]
    const int b = bh >> 4;     // HN = 16
    const int h = bh & 15;
#pragma unroll
    for (int i = 0; i < 4; i++) {
        size_t off = ((size_t)b * LSEQ + q0 + w * 4 + i) * DM + h * DH + 2 * lane;
        *(float2*)&out[off] = make_float2(o[i][0], o[i][1]);
    }
}

// ---------------------------------------------------------------------------
extern "C" void kernel_launch(void* const* d_in, const int* in_sizes, int n_in,
                              void* d_out, int out_size) {
    const float* q_in = (const float*)d_in[0];
    const float* k_in = (const float*)d_in[1];
    const float* v_in = (const float*)d_in[2];
    const float* wq   = (const float*)d_in[3];
    const float* wk   = (const float*)d_in[4];
    const float* wv   = (const float*)d_in[5];

    float *qb, *kb, *vb, *attn_scratch, *out_scratch;
    cudaGetSymbolAddress((void**)&qb, g_q);
    cudaGetSymbolAddress((void**)&kb, g_k);
    cudaGetSymbolAddress((void**)&vb, g_v);
    cudaGetSymbolAddress((void**)&attn_scratch, g_attn);
    cudaGetSymbolAddress((void**)&out_scratch, g_outs);

    const long long out_elems  = (long long)BSZ * LSEQ * DM;          // 8388608
    const long long attn_elems = (long long)BSZ * HN * LSEQ * LSEQ;   // 268435456

    float* out_ptr  = (float*)d_out;
    float* attn_ptr = attn_scratch;
    long long osz = (long long)out_size;
    if (osz >= out_elems + attn_elems) {
        attn_ptr = (float*)d_out + out_elems;          // output = (out, attn)
    } else if (osz == attn_elems) {
        attn_ptr = (float*)d_out;                       // output = attn only
        out_ptr  = out_scratch;
    }                                                   // else: out only

    dim3 pgrid(DM / 64, (BSZ * LSEQ) / 64);
    dim3 pblk(16, 16);
    proj_kernel<<<pgrid, pblk>>>(q_in, wq, qb);
    proj_kernel<<<pgrid, pblk>>>(k_in, wk, kb);
    proj_kernel<<<pgrid, pblk>>>(v_in, wv, vb);

    dim3 agrid(LSEQ / 32, BSZ * HN);
    attn_kernel<<<agrid, 256>>>(attn_ptr, out_ptr);
}

// round 8
// speedup vs baseline: 1.5717x; 1.4925x over previous
#include <cuda_runtime.h>
#include <cuda_bf16.h>
#include <cstdint>
#include <math.h>

#define BSZ 4
#define HN 16
#define LSEQ 2048
#define DM 1024
#define DH 64
#define NBH (BSZ*HN)

// ---------------- device scratch ----------------
__device__ __nv_bfloat16 g_xh[(size_t)BSZ*LSEQ*DM];
__device__ __nv_bfloat16 g_xl[(size_t)BSZ*LSEQ*DM];
__device__ __nv_bfloat16 g_wh[(size_t)DM*DM];
__device__ __nv_bfloat16 g_wl[(size_t)DM*DM];
__device__ __nv_bfloat16 g_qh[(size_t)NBH*LSEQ*DH];
__device__ __nv_bfloat16 g_ql[(size_t)NBH*LSEQ*DH];
__device__ __nv_bfloat16 g_kh[(size_t)NBH*LSEQ*DH];
__device__ __nv_bfloat16 g_kl[(size_t)NBH*LSEQ*DH];
__device__ __nv_bfloat16 g_vh[(size_t)NBH*LSEQ*DH];
__device__ __nv_bfloat16 g_vl[(size_t)NBH*LSEQ*DH];
__device__ float g_rowp[(size_t)NBH*LSEQ*64];
__device__ float g_rinv[(size_t)NBH*LSEQ];
__device__ float g_attn_s[(size_t)NBH*LSEQ*LSEQ];
__device__ float g_outs[(size_t)BSZ*LSEQ*DM];

// ---------------- smem offsets ----------------
#define P_AH 0
#define P_AL 16384
#define P_BH 32768
#define P_BL 49152
#define SMEM_GEMM 66560          // also covers score E staging 128*130*4

#define V_PH 0
#define V_PL 16384
#define V_VH 32768
#define V_VL 40960
#define V_RINV 49152
#define SMEM_PV 49664

// ---------------- warp mma helpers ----------------
__device__ __forceinline__ uint32_t smem_u32(const void* p) {
    uint32_t a;
    asm("{ .reg .u64 t; cvta.to.shared.u64 t, %1; cvt.u32.u64 %0, t; }" : "=r"(a) : "l"(p));
    return a;
}
__device__ __forceinline__ uint32_t swz(uint32_t base, int r, int cb) {
    uint32_t off = (uint32_t)(r * 128 + cb);
    return base + (off ^ ((off >> 3) & 0x70));
}
__device__ __forceinline__ void ldsm4(uint32_t* r, uint32_t a) {
    asm volatile("ldmatrix.sync.aligned.m8n8.x4.shared.b16 {%0,%1,%2,%3}, [%4];"
        : "=r"(r[0]), "=r"(r[1]), "=r"(r[2]), "=r"(r[3]) : "r"(a));
}
__device__ __forceinline__ void ldsm4t(uint32_t* r, uint32_t a) {
    asm volatile("ldmatrix.sync.aligned.m8n8.x4.trans.shared.b16 {%0,%1,%2,%3}, [%4];"
        : "=r"(r[0]), "=r"(r[1]), "=r"(r[2]), "=r"(r[3]) : "r"(a));
}
__device__ __forceinline__ void mma16816(float* c, const uint32_t* a, const uint32_t* b) {
    asm volatile("mma.sync.aligned.m16n8k16.row.col.f32.bf16.bf16.f32 "
        "{%0,%1,%2,%3}, {%4,%5,%6,%7}, {%8,%9}, {%0,%1,%2,%3};"
        : "+f"(c[0]), "+f"(c[1]), "+f"(c[2]), "+f"(c[3])
        : "r"(a[0]), "r"(a[1]), "r"(a[2]), "r"(a[3]), "r"(b[0]), "r"(b[1]));
}

// ---------------- math helpers ----------------
__device__ __forceinline__ void split2(float a, float b, uint32_t& hp, uint32_t& lp) {
    __nv_bfloat16 ah = __float2bfloat16(a), bh = __float2bfloat16(b);
    float al = a - __bfloat162float(ah);
    float bl = b - __bfloat162float(bh);
    __nv_bfloat162 hv; hv.x = ah; hv.y = bh;
    __nv_bfloat162 lv; lv.x = __float2bfloat16(al); lv.y = __float2bfloat16(bl);
    hp = *reinterpret_cast<uint32_t*>(&hv);
    lp = *reinterpret_cast<uint32_t*>(&lv);
}
// exp(raw/8) via FFMA polynomial (268M exps; MUFU would bottleneck)
__device__ __forceinline__ float fast_exp8(float raw) {
    float y = raw * 0.180336880090206f;          // (1/8)*log2(e)
    int n = __float2int_rn(y);
    float f = y - (float)n;
    float p = 1.54035304e-4f;
    p = fmaf(p, f, 1.33335581e-3f);
    p = fmaf(p, f, 9.61812911e-3f);
    p = fmaf(p, f, 5.55041087e-2f);
    p = fmaf(p, f, 2.40226507e-1f);
    p = fmaf(p, f, 6.93147181e-1f);
    p = fmaf(p, f, 1.0f);
    return p * __int_as_float((n + 127) << 23);
}

// ===========================================================================
// convert: fp32 -> (hi, lo) bf16
// ===========================================================================
__global__ void convert_kernel(const float* __restrict__ src,
                               __nv_bfloat16* __restrict__ hi,
                               __nv_bfloat16* __restrict__ lo, int n4) {
    int i = blockIdx.x * blockDim.x + threadIdx.x;
    if (i < n4) {
        float4 v = reinterpret_cast<const float4*>(src)[i];
        uint32_t h0, l0, h1, l1;
        split2(v.x, v.y, h0, l0);
        split2(v.z, v.w, h1, l1);
        reinterpret_cast<uint2*>(hi)[i] = make_uint2(h0, h1);
        reinterpret_cast<uint2*>(lo)[i] = make_uint2(l0, l1);
    }
}

// ===========================================================================
// Warp-tile MMA core: 64x32 warp tile (4 m-tiles x 4 n-tiles), K-chunk 64,
// 3 hi/lo terms. smem tiles [128][64] bf16, SW128 swizzle.
// ===========================================================================
__device__ __forceinline__ void mma_block_64(
    float C[4][4][4], uint32_t ah, uint32_t al, uint32_t bh, uint32_t bl,
    int m_base, int n_base, int lane)
{
#pragma unroll
    for (int term = 0; term < 3; term++) {
        uint32_t As = (term == 2) ? al : ah;
        uint32_t Bs = (term == 1) ? bl : bh;
#pragma unroll
        for (int ks = 0; ks < 4; ks++) {
            uint32_t a[4][4];
#pragma unroll
            for (int mt = 0; mt < 4; mt++)
                ldsm4(a[mt], swz(As, m_base + mt * 16 + (lane & 15), ks * 32 + (lane >> 4) * 16));
            uint32_t b[4][2];
            const int mg = lane >> 3, rs = lane & 7;
#pragma unroll
            for (int p = 0; p < 2; p++) {
                uint32_t r4[4];
                int row = n_base + p * 16 + ((mg >= 2) ? 8 : 0) + rs;
                int cb = ks * 32 + (mg & 1) * 16;
                ldsm4(r4, swz(Bs, row, cb));
                b[2 * p][0] = r4[0]; b[2 * p][1] = r4[1];
                b[2 * p + 1][0] = r4[2]; b[2 * p + 1][1] = r4[3];
            }
#pragma unroll
            for (int mt = 0; mt < 4; mt++)
#pragma unroll
                for (int nt = 0; nt < 4; nt++)
                    mma16816(C[mt][nt], a[mt], b[nt]);
        }
    }
}

// ===========================================================================
// Stage A: Y = X @ W^T -> head-major hi/lo [bh][l][64]
// grid (DM/128=8, M/128=64), 256 thr (8 warps, 2x4 warp grid)
// ===========================================================================
__global__ void __launch_bounds__(256) proj_kernel(
    const __nv_bfloat16* __restrict__ xh, const __nv_bfloat16* __restrict__ xl,
    const __nv_bfloat16* __restrict__ wh, const __nv_bfloat16* __restrict__ wl,
    __nv_bfloat16* __restrict__ oh, __nv_bfloat16* __restrict__ ol)
{
    extern __shared__ char smem[];
    const uint32_t sb = smem_u32(smem);
    const int tid = threadIdx.x, wid = tid >> 5, lane = tid & 31;
    const int n0 = blockIdx.x * 128, m0 = blockIdx.y * 128;
    const int m_base = (wid & 1) * 64, n_base = (wid >> 1) * 32;

    float C[4][4][4] = {};

    for (int ck = 0; ck < 16; ck++) {
        const int k0 = ck * 64;
        for (int i = tid; i < 1024; i += 256) {
            int r = i >> 3, c8 = (i & 7) * 8;
            uint32_t d = swz(sb, r, c8 * 2);
            size_t ga = (size_t)(m0 + r) * DM + k0 + c8;
            size_t gb = (size_t)(n0 + r) * DM + k0 + c8;
            *reinterpret_cast<uint4*>(smem + (d - sb) + P_AH) = *reinterpret_cast<const uint4*>(&xh[ga]);
            *reinterpret_cast<uint4*>(smem + (d - sb) + P_AL) = *reinterpret_cast<const uint4*>(&xl[ga]);
            *reinterpret_cast<uint4*>(smem + (d - sb) + P_BH) = *reinterpret_cast<const uint4*>(&wh[gb]);
            *reinterpret_cast<uint4*>(smem + (d - sb) + P_BL) = *reinterpret_cast<const uint4*>(&wl[gb]);
        }
        __syncthreads();
        mma_block_64(C, sb + P_AH, sb + P_AL, sb + P_BH, sb + P_BL, m_base, n_base, lane);
        __syncthreads();
    }

    // Epilogue: split hi/lo -> [bh][l][64]
#pragma unroll
    for (int mt = 0; mt < 4; mt++) {
#pragma unroll
        for (int nt = 0; nt < 4; nt++) {
            int n = n0 + n_base + nt * 8 + 2 * (lane & 3);
            int h = n >> 6, dd = n & 63;
#pragma unroll
            for (int half = 0; half < 2; half++) {
                int m = m0 + m_base + mt * 16 + (lane >> 2) + half * 8;
                int b = m >> 11, l = m & (LSEQ - 1);
                uint32_t hp, lp;
                split2(C[mt][nt][half * 2], C[mt][nt][half * 2 + 1], hp, lp);
                size_t base = (((size_t)(b * HN + h)) * LSEQ + l) * DH + dd;
                *reinterpret_cast<uint32_t*>(&oh[base]) = hp;
                *reinterpret_cast<uint32_t*>(&ol[base]) = lp;
            }
        }
    }
}

// ===========================================================================
// Stage B: E = exp(QK^T/8) + per-warp row partials.
// grid (nt=16, mt=16, bh=64), 256 thr.
// ===========================================================================
__global__ void __launch_bounds__(256) score_kernel(
    const __nv_bfloat16* __restrict__ qh, const __nv_bfloat16* __restrict__ ql,
    const __nv_bfloat16* __restrict__ kh, const __nv_bfloat16* __restrict__ kl,
    float* __restrict__ attn, float* __restrict__ rowp)
{
    extern __shared__ char smem[];
    const uint32_t sb = smem_u32(smem);
    const int tid = threadIdx.x, wid = tid >> 5, lane = tid & 31;
    const int nt_blk = blockIdx.x, mt_blk = blockIdx.y, bh = blockIdx.z;
    const int n0 = nt_blk * 128, m0 = mt_blk * 128;
    const int m_base = (wid & 1) * 64, n_base = (wid >> 1) * 32;

    // load Q,K tiles [128][64] hi/lo
    {
        const __nv_bfloat16* sp[4] = {
            qh + ((size_t)bh * LSEQ + m0) * DH, ql + ((size_t)bh * LSEQ + m0) * DH,
            kh + ((size_t)bh * LSEQ + n0) * DH, kl + ((size_t)bh * LSEQ + n0) * DH };
        const int so[4] = {P_AH, P_AL, P_BH, P_BL};
#pragma unroll
        for (int a = 0; a < 4; a++)
            for (int i = tid; i < 1024; i += 256) {
                int r = i >> 3, c8 = (i & 7) * 8;
                uint32_t d = swz(sb, r, c8 * 2) - sb;
                *reinterpret_cast<uint4*>(smem + so[a] + d) =
                    *reinterpret_cast<const uint4*>(&sp[a][(size_t)r * DH + c8]);
            }
    }
    __syncthreads();

    float C[4][4][4] = {};
    mma_block_64(C, sb + P_AH, sb + P_AL, sb + P_BH, sb + P_BL, m_base, n_base, lane);
    __syncthreads();   // tiles dead; smem becomes E staging [128][130] f32

    float* E = reinterpret_cast<float*>(smem);
    float sloc[4][2] = {};
#pragma unroll
    for (int mt = 0; mt < 4; mt++)
#pragma unroll
        for (int nt = 0; nt < 4; nt++)
#pragma unroll
            for (int half = 0; half < 2; half++) {
                float e0 = fast_exp8(C[mt][nt][half * 2]);
                float e1 = fast_exp8(C[mt][nt][half * 2 + 1]);
                sloc[mt][half] += e0 + e1;
                int row = m_base + mt * 16 + (lane >> 2) + half * 8;
                int col = n_base + nt * 8 + 2 * (lane & 3);
                *reinterpret_cast<float2*>(&E[row * 130 + col]) = make_float2(e0, e1);
            }

    // deterministic row partials: reduce over lane%4, write (nt_blk*4 + warp_n)
#pragma unroll
    for (int mt = 0; mt < 4; mt++)
#pragma unroll
        for (int half = 0; half < 2; half++) {
            float v = sloc[mt][half];
            v += __shfl_xor_sync(0xFFFFFFFFu, v, 1);
            v += __shfl_xor_sync(0xFFFFFFFFu, v, 2);
            if ((lane & 3) == 0) {
                int row = m0 + m_base + mt * 16 + (lane >> 2) + half * 8;
                rowp[((size_t)bh * LSEQ + row) * 64 + nt_blk * 4 + (wid >> 1)] = v;
            }
        }
    __syncthreads();

    float* ap = attn + ((size_t)bh * LSEQ + m0) * LSEQ + n0;
    for (int i = tid; i < 128 * 128; i += 256) {
        int r = i >> 7, c = i & 127;
        ap[(size_t)r * LSEQ + c] = E[r * 130 + c];
    }
}

__global__ void rowsum_kernel(const float* __restrict__ rowp, float* __restrict__ rinv) {
    int i = blockIdx.x * blockDim.x + threadIdx.x;
    if (i < NBH * LSEQ) {
        float s = 0.f;
#pragma unroll
        for (int j = 0; j < 64; j++) s += rowp[(size_t)i * 64 + j];
        rinv[i] = 1.0f / s;
    }
}

// ===========================================================================
// Stage C: normalize attn in place (final output) + O = P@V.
// grid (mt=16, bh=64), 256 thr. warp tile 32x32 (4x2 warp grid).
// B = V via ldmatrix.trans (V stored [bh][l][64] like Q/K).
// ===========================================================================
__global__ void __launch_bounds__(256) pv_kernel(
    float* __restrict__ attn,
    const __nv_bfloat16* __restrict__ vh, const __nv_bfloat16* __restrict__ vl,
    const float* __restrict__ rinv, float* __restrict__ out)
{
    extern __shared__ char smem[];
    const uint32_t sb = smem_u32(smem);
    const int tid = threadIdx.x, wid = tid >> 5, lane = tid & 31;
    const int mt_blk = blockIdx.x, bh = blockIdx.y;
    const int m0 = mt_blk * 128;
    const int m_base = (wid & 3) * 32, n_base = (wid >> 2) * 32;

    float* srinv = reinterpret_cast<float*>(smem + V_RINV);
    if (tid < 128) srinv[tid] = rinv[(size_t)bh * LSEQ + m0 + tid];
    __syncthreads();

    float* apb = attn + ((size_t)bh * LSEQ + m0) * LSEQ;
    const __nv_bfloat16* vhb = vh + (size_t)bh * LSEQ * DH;
    const __nv_bfloat16* vlb = vl + (size_t)bh * LSEQ * DH;

    float C[2][4][4] = {};

    for (int ck = 0; ck < 32; ck++) {
        const int k0 = ck * 64;
        // P: read E, normalize, write final attn, split hi/lo
        for (int i = tid; i < 2048; i += 256) {
            int r = i >> 4, c4 = (i & 15) * 4;
            float4* addr = reinterpret_cast<float4*>(&apb[(size_t)r * LSEQ + k0 + c4]);
            float4 e = *addr;
            float ri = srinv[r];
            e.x *= ri; e.y *= ri; e.z *= ri; e.w *= ri;
            *addr = e;
            uint32_t h0, l0, h1, l1;
            split2(e.x, e.y, h0, l0);
            split2(e.z, e.w, h1, l1);
            uint32_t d = swz(sb, r, c4 * 2) - sb;
            *reinterpret_cast<uint2*>(smem + V_PH + d) = make_uint2(h0, h1);
            *reinterpret_cast<uint2*>(smem + V_PL + d) = make_uint2(l0, l1);
        }
        // V chunk [64][64]
        for (int i = tid; i < 512; i += 256) {
            int r = i >> 3, c8 = (i & 7) * 8;
            uint32_t d = swz(sb, r, c8 * 2) - sb;
            size_t ga = (size_t)(k0 + r) * DH + c8;
            *reinterpret_cast<uint4*>(smem + V_VH + d) = *reinterpret_cast<const uint4*>(&vhb[ga]);
            *reinterpret_cast<uint4*>(smem + V_VL + d) = *reinterpret_cast<const uint4*>(&vlb[ga]);
        }
        __syncthreads();

#pragma unroll
        for (int term = 0; term < 3; term++) {
            uint32_t As = sb + ((term == 2) ? V_PL : V_PH);
            uint32_t Bs = sb + ((term == 1) ? V_VL : V_VH);
#pragma unroll
            for (int ks = 0; ks < 4; ks++) {
                uint32_t a[2][4];
#pragma unroll
                for (int mt = 0; mt < 2; mt++)
                    ldsm4(a[mt], swz(As, m_base + mt * 16 + (lane & 15), ks * 32 + (lane >> 4) * 16));
                uint32_t b[4][2];
                const int mg = lane >> 3, rs = lane & 7;
#pragma unroll
                for (int p = 0; p < 2; p++) {
                    uint32_t r4[4];
                    int row = ks * 16 + (mg & 1) * 8 + rs;
                    int cb = (n_base + p * 16 + ((mg >= 2) ? 8 : 0)) * 2;
                    ldsm4t(r4, swz(Bs, row, cb));
                    b[2 * p][0] = r4[0]; b[2 * p][1] = r4[1];
                    b[2 * p + 1][0] = r4[2]; b[2 * p + 1][1] = r4[3];
                }
#pragma unroll
                for (int mt = 0; mt < 2; mt++)
#pragma unroll
                    for (int nt = 0; nt < 4; nt++)
                        mma16816(C[mt][nt], a[mt], b[nt]);
            }
        }
        __syncthreads();
    }

    // Epilogue: out[b][l][h*64 + d]
    const int b = bh >> 4, h = bh & 15;
#pragma unroll
    for (int mt = 0; mt < 2; mt++)
#pragma unroll
        for (int nt = 0; nt < 4; nt++) {
            int n = n_base + nt * 8 + 2 * (lane & 3);
#pragma unroll
            for (int half = 0; half < 2; half++) {
                int m = m0 + m_base + mt * 16 + (lane >> 2) + half * 8;
                *reinterpret_cast<float2*>(&out[((size_t)b * LSEQ + m) * DM + h * DH + n]) =
                    make_float2(C[mt][nt][half * 2], C[mt][nt][half * 2 + 1]);
            }
        }
}

// ===========================================================================
extern "C" void kernel_launch(void* const* d_in, const int* in_sizes, int n_in,
                              void* d_out, int out_size) {
    const float* q_in = (const float*)d_in[0];
    const float* k_in = (const float*)d_in[1];
    const float* v_in = (const float*)d_in[2];
    const float* wq   = (const float*)d_in[3];
    const float* wk   = (const float*)d_in[4];
    const float* wv   = (const float*)d_in[5];

    __nv_bfloat16 *xh, *xl, *wh, *wl, *qh, *ql, *kh, *kl, *vh, *vl;
    float *rowp, *rinv, *attn_scratch, *out_scratch;
    cudaGetSymbolAddress((void**)&xh, g_xh);
    cudaGetSymbolAddress((void**)&xl, g_xl);
    cudaGetSymbolAddress((void**)&wh, g_wh);
    cudaGetSymbolAddress((void**)&wl, g_wl);
    cudaGetSymbolAddress((void**)&qh, g_qh);
    cudaGetSymbolAddress((void**)&ql, g_ql);
    cudaGetSymbolAddress((void**)&kh, g_kh);
    cudaGetSymbolAddress((void**)&kl, g_kl);
    cudaGetSymbolAddress((void**)&vh, g_vh);
    cudaGetSymbolAddress((void**)&vl, g_vl);
    cudaGetSymbolAddress((void**)&rowp, g_rowp);
    cudaGetSymbolAddress((void**)&rinv, g_rinv);
    cudaGetSymbolAddress((void**)&attn_scratch, g_attn_s);
    cudaGetSymbolAddress((void**)&out_scratch, g_outs);

    const long long out_elems  = (long long)BSZ * LSEQ * DM;
    const long long attn_elems = (long long)NBH * LSEQ * LSEQ;

    float* out_ptr  = (float*)d_out;
    float* attn_ptr = attn_scratch;
    long long osz = (long long)out_size;
    if (osz >= out_elems + attn_elems) {
        attn_ptr = (float*)d_out + out_elems;
    } else if (osz == attn_elems) {
        attn_ptr = (float*)d_out;
        out_ptr  = out_scratch;
    }

    cudaFuncSetAttribute(proj_kernel,  cudaFuncAttributeMaxDynamicSharedMemorySize, SMEM_GEMM);
    cudaFuncSetAttribute(score_kernel, cudaFuncAttributeMaxDynamicSharedMemorySize, SMEM_GEMM);
    cudaFuncSetAttribute(pv_kernel,    cudaFuncAttributeMaxDynamicSharedMemorySize, SMEM_PV);

    const int xn4 = (BSZ * LSEQ * DM) / 4;
    const int wn4 = (DM * DM) / 4;
    dim3 pgrid(DM / 128, (BSZ * LSEQ) / 128);

    convert_kernel<<<(xn4 + 255) / 256, 256>>>(q_in, xh, xl, xn4);
    convert_kernel<<<(wn4 + 255) / 256, 256>>>(wq, wh, wl, wn4);
    proj_kernel<<<pgrid, 256, SMEM_GEMM>>>(xh, xl, wh, wl, qh, ql);

    convert_kernel<<<(xn4 + 255) / 256, 256>>>(k_in, xh, xl, xn4);
    convert_kernel<<<(wn4 + 255) / 256, 256>>>(wk, wh, wl, wn4);
    proj_kernel<<<pgrid, 256, SMEM_GEMM>>>(xh, xl, wh, wl, kh, kl);

    convert_kernel<<<(xn4 + 255) / 256, 256>>>(v_in, xh, xl, xn4);
    convert_kernel<<<(wn4 + 255) / 256, 256>>>(wv, wh, wl, wn4);
    proj_kernel<<<pgrid, 256, SMEM_GEMM>>>(xh, xl, wh, wl, vh, vl);

    score_kernel<<<dim3(16, 16, NBH), 256, SMEM_GEMM>>>(qh, ql, kh, kl, attn_ptr, rowp);
    rowsum_kernel<<<(NBH * LSEQ + 255) / 256, 256>>>(rowp, rinv);
    pv_kernel<<<dim3(16, NBH), 256, SMEM_PV>>>(attn_ptr, vh, vl, rinv, out_ptr);
}

// round 9
// speedup vs baseline: 1.7950x; 1.1420x over previous
#include <cuda_runtime.h>
#include <cuda_bf16.h>
#include <cstdint>
#include <math.h>

#define BSZ 4
#define HN 16
#define LSEQ 2048
#define DM 1024
#define DH 64
#define NBH (BSZ*HN)

// ---------------- device scratch ----------------
__device__ __nv_bfloat16 g_xh[(size_t)BSZ*LSEQ*DM];
__device__ __nv_bfloat16 g_xl[(size_t)BSZ*LSEQ*DM];
__device__ __nv_bfloat16 g_wh[(size_t)DM*DM];
__device__ __nv_bfloat16 g_wl[(size_t)DM*DM];
__device__ __nv_bfloat16 g_qh[(size_t)NBH*LSEQ*DH];
__device__ __nv_bfloat16 g_ql[(size_t)NBH*LSEQ*DH];
__device__ __nv_bfloat16 g_kh[(size_t)NBH*LSEQ*DH];
__device__ __nv_bfloat16 g_kl[(size_t)NBH*LSEQ*DH];
__device__ __nv_bfloat16 g_vh[(size_t)NBH*LSEQ*DH];
__device__ __nv_bfloat16 g_vl[(size_t)NBH*LSEQ*DH];
__device__ float g_rowp[(size_t)NBH*LSEQ*64];
__device__ float g_rinv[(size_t)NBH*LSEQ];
__device__ float g_attn_s[(size_t)NBH*LSEQ*LSEQ];
__device__ float g_outs[(size_t)BSZ*LSEQ*DM];

// ---------------- smem offsets ----------------
// proj: two pipeline stages of 4 tiles [128][64] bf16
#define P_AH 0
#define P_AL 16384
#define P_BH 32768
#define P_BL 49152
#define PSTAGE 65536
#define SMEM_PROJ 131072

#define SMEM_SCORE 66560         // 4 tiles + E staging reuse (128*130*4)

#define V_PH 0
#define V_PL 16384
#define V_VH 32768
#define V_VL 40960
#define V_RINV 49152
#define SMEM_PV 49664

// ---------------- async copy helpers ----------------
__device__ __forceinline__ void cpasync16(uint32_t saddr, const void* g) {
    asm volatile("cp.async.cg.shared.global [%0], [%1], 16;" :: "r"(saddr), "l"(g));
}
#define CP_COMMIT()  asm volatile("cp.async.commit_group;")
#define CP_WAIT(N)   asm volatile("cp.async.wait_group %0;" :: "n"(N))

// ---------------- warp mma helpers ----------------
__device__ __forceinline__ uint32_t smem_u32(const void* p) {
    uint32_t a;
    asm("{ .reg .u64 t; cvta.to.shared.u64 t, %1; cvt.u32.u64 %0, t; }" : "=r"(a) : "l"(p));
    return a;
}
__device__ __forceinline__ uint32_t swz(uint32_t base, int r, int cb) {
    uint32_t off = (uint32_t)(r * 128 + cb);
    return base + (off ^ ((off >> 3) & 0x70));
}
__device__ __forceinline__ void ldsm4(uint32_t* r, uint32_t a) {
    asm volatile("ldmatrix.sync.aligned.m8n8.x4.shared.b16 {%0,%1,%2,%3}, [%4];"
        : "=r"(r[0]), "=r"(r[1]), "=r"(r[2]), "=r"(r[3]) : "r"(a));
}
__device__ __forceinline__ void ldsm4t(uint32_t* r, uint32_t a) {
    asm volatile("ldmatrix.sync.aligned.m8n8.x4.trans.shared.b16 {%0,%1,%2,%3}, [%4];"
        : "=r"(r[0]), "=r"(r[1]), "=r"(r[2]), "=r"(r[3]) : "r"(a));
}
__device__ __forceinline__ void mma16816(float* c, const uint32_t* a, const uint32_t* b) {
    asm volatile("mma.sync.aligned.m16n8k16.row.col.f32.bf16.bf16.f32 "
        "{%0,%1,%2,%3}, {%4,%5,%6,%7}, {%8,%9}, {%0,%1,%2,%3};"
        : "+f"(c[0]), "+f"(c[1]), "+f"(c[2]), "+f"(c[3])
        : "r"(a[0]), "r"(a[1]), "r"(a[2]), "r"(a[3]), "r"(b[0]), "r"(b[1]));
}

// ---------------- math helpers ----------------
__device__ __forceinline__ void split2(float a, float b, uint32_t& hp, uint32_t& lp) {
    __nv_bfloat16 ah = __float2bfloat16(a), bh = __float2bfloat16(b);
    float al = a - __bfloat162float(ah);
    float bl = b - __bfloat162float(bh);
    __nv_bfloat162 hv; hv.x = ah; hv.y = bh;
    __nv_bfloat162 lv; lv.x = __float2bfloat16(al); lv.y = __float2bfloat16(bl);
    hp = *reinterpret_cast<uint32_t*>(&hv);
    lp = *reinterpret_cast<uint32_t*>(&lv);
}
__device__ __forceinline__ float fast_exp8(float raw) {
    float y = raw * 0.180336880090206f;          // (1/8)*log2(e)
    int n = __float2int_rn(y);
    float f = y - (float)n;
    float p = 1.54035304e-4f;
    p = fmaf(p, f, 1.33335581e-3f);
    p = fmaf(p, f, 9.61812911e-3f);
    p = fmaf(p, f, 5.55041087e-2f);
    p = fmaf(p, f, 2.40226507e-1f);
    p = fmaf(p, f, 6.93147181e-1f);
    p = fmaf(p, f, 1.0f);
    return p * __int_as_float((n + 127) << 23);
}

// ===========================================================================
__global__ void convert_kernel(const float* __restrict__ src,
                               __nv_bfloat16* __restrict__ hi,
                               __nv_bfloat16* __restrict__ lo, int n4) {
    int i = blockIdx.x * blockDim.x + threadIdx.x;
    if (i < n4) {
        float4 v = reinterpret_cast<const float4*>(src)[i];
        uint32_t h0, l0, h1, l1;
        split2(v.x, v.y, h0, l0);
        split2(v.z, v.w, h1, l1);
        reinterpret_cast<uint2*>(hi)[i] = make_uint2(h0, h1);
        reinterpret_cast<uint2*>(lo)[i] = make_uint2(l0, l1);
    }
}

// ===========================================================================
// Warp-tile MMA core: 64x32 warp tile, K-chunk 64, 3 hi/lo terms.
// ===========================================================================
__device__ __forceinline__ void mma_block_64(
    float C[4][4][4], uint32_t ah, uint32_t al, uint32_t bh, uint32_t bl,
    int m_base, int n_base, int lane)
{
#pragma unroll
    for (int term = 0; term < 3; term++) {
        uint32_t As = (term == 2) ? al : ah;
        uint32_t Bs = (term == 1) ? bl : bh;
#pragma unroll
        for (int ks = 0; ks < 4; ks++) {
            uint32_t a[4][4];
#pragma unroll
            for (int mt = 0; mt < 4; mt++)
                ldsm4(a[mt], swz(As, m_base + mt * 16 + (lane & 15), ks * 32 + (lane >> 4) * 16));
            uint32_t b[4][2];
            const int mg = lane >> 3, rs = lane & 7;
#pragma unroll
            for (int p = 0; p < 2; p++) {
                uint32_t r4[4];
                int row = n_base + p * 16 + ((mg >= 2) ? 8 : 0) + rs;
                int cb = ks * 32 + (mg & 1) * 16;
                ldsm4(r4, swz(Bs, row, cb));
                b[2 * p][0] = r4[0]; b[2 * p][1] = r4[1];
                b[2 * p + 1][0] = r4[2]; b[2 * p + 1][1] = r4[3];
            }
#pragma unroll
            for (int mt = 0; mt < 4; mt++)
#pragma unroll
                for (int nt = 0; nt < 4; nt++)
                    mma16816(C[mt][nt], a[mt], b[nt]);
        }
    }
}

// ===========================================================================
// Stage A: Y = X @ W^T, 2-stage cp.async pipeline over 16 K-chunks.
// grid (8, 64), 256 thr.
// ===========================================================================
__global__ void __launch_bounds__(256) proj_kernel(
    const __nv_bfloat16* __restrict__ xh, const __nv_bfloat16* __restrict__ xl,
    const __nv_bfloat16* __restrict__ wh, const __nv_bfloat16* __restrict__ wl,
    __nv_bfloat16* __restrict__ oh, __nv_bfloat16* __restrict__ ol)
{
    extern __shared__ char smem[];
    const uint32_t sb = smem_u32(smem);
    const int tid = threadIdx.x, wid = tid >> 5, lane = tid & 31;
    const int n0 = blockIdx.x * 128, m0 = blockIdx.y * 128;
    const int m_base = (wid & 1) * 64, n_base = (wid >> 1) * 32;

    auto load_chunk = [&](int ck, int stage) {
        const int k0 = ck * 64;
        const uint32_t st = sb + stage * PSTAGE;
        for (int i = tid; i < 1024; i += 256) {
            int r = i >> 3, c8 = (i & 7) * 8;
            uint32_t d = swz((uint32_t)0, r, c8 * 2);
            size_t ga = (size_t)(m0 + r) * DM + k0 + c8;
            size_t gb = (size_t)(n0 + r) * DM + k0 + c8;
            cpasync16(st + P_AH + d, &xh[ga]);
            cpasync16(st + P_AL + d, &xl[ga]);
            cpasync16(st + P_BH + d, &wh[gb]);
            cpasync16(st + P_BL + d, &wl[gb]);
        }
        CP_COMMIT();
    };

    float C[4][4][4] = {};
    load_chunk(0, 0);
    for (int ck = 0; ck < 16; ck++) {
        const int stage = ck & 1;
        if (ck + 1 < 16) { load_chunk(ck + 1, (ck + 1) & 1); CP_WAIT(1); }
        else             { CP_WAIT(0); }
        __syncthreads();
        const uint32_t st = sb + stage * PSTAGE;
        mma_block_64(C, st + P_AH, st + P_AL, st + P_BH, st + P_BL, m_base, n_base, lane);
        __syncthreads();
    }

#pragma unroll
    for (int mt = 0; mt < 4; mt++) {
#pragma unroll
        for (int nt = 0; nt < 4; nt++) {
            int n = n0 + n_base + nt * 8 + 2 * (lane & 3);
            int h = n >> 6, dd = n & 63;
#pragma unroll
            for (int half = 0; half < 2; half++) {
                int m = m0 + m_base + mt * 16 + (lane >> 2) + half * 8;
                int b = m >> 11, l = m & (LSEQ - 1);
                uint32_t hp, lp;
                split2(C[mt][nt][half * 2], C[mt][nt][half * 2 + 1], hp, lp);
                size_t base = (((size_t)(b * HN + h)) * LSEQ + l) * DH + dd;
                *reinterpret_cast<uint32_t*>(&oh[base]) = hp;
                *reinterpret_cast<uint32_t*>(&ol[base]) = lp;
            }
        }
    }
}

// ===========================================================================
// Stage B: E = exp(QK^T/8) + per-warp row partials.
// ===========================================================================
__global__ void __launch_bounds__(256) score_kernel(
    const __nv_bfloat16* __restrict__ qh, const __nv_bfloat16* __restrict__ ql,
    const __nv_bfloat16* __restrict__ kh, const __nv_bfloat16* __restrict__ kl,
    float* __restrict__ attn, float* __restrict__ rowp)
{
    extern __shared__ char smem[];
    const uint32_t sb = smem_u32(smem);
    const int tid = threadIdx.x, wid = tid >> 5, lane = tid & 31;
    const int nt_blk = blockIdx.x, mt_blk = blockIdx.y, bh = blockIdx.z;
    const int n0 = nt_blk * 128, m0 = mt_blk * 128;
    const int m_base = (wid & 1) * 64, n_base = (wid >> 1) * 32;

    {
        const __nv_bfloat16* sp[4] = {
            qh + ((size_t)bh * LSEQ + m0) * DH, ql + ((size_t)bh * LSEQ + m0) * DH,
            kh + ((size_t)bh * LSEQ + n0) * DH, kl + ((size_t)bh * LSEQ + n0) * DH };
        const int so[4] = {0, 16384, 32768, 49152};
#pragma unroll
        for (int a = 0; a < 4; a++)
            for (int i = tid; i < 1024; i += 256) {
                int r = i >> 3, c8 = (i & 7) * 8;
                uint32_t d = swz((uint32_t)0, r, c8 * 2);
                cpasync16(sb + so[a] + d, &sp[a][(size_t)r * DH + c8]);
            }
        CP_COMMIT(); CP_WAIT(0);
    }
    __syncthreads();

    float C[4][4][4] = {};
    mma_block_64(C, sb + 0, sb + 16384, sb + 32768, sb + 49152, m_base, n_base, lane);
    __syncthreads();   // tiles dead; smem becomes E staging [128][130] f32

    float* E = reinterpret_cast<float*>(smem);
    float sloc[4][2] = {};
#pragma unroll
    for (int mt = 0; mt < 4; mt++)
#pragma unroll
        for (int nt = 0; nt < 4; nt++)
#pragma unroll
            for (int half = 0; half < 2; half++) {
                float e0 = fast_exp8(C[mt][nt][half * 2]);
                float e1 = fast_exp8(C[mt][nt][half * 2 + 1]);
                sloc[mt][half] += e0 + e1;
                int row = m_base + mt * 16 + (lane >> 2) + half * 8;
                int col = n_base + nt * 8 + 2 * (lane & 3);
                *reinterpret_cast<float2*>(&E[row * 130 + col]) = make_float2(e0, e1);
            }

#pragma unroll
    for (int mt = 0; mt < 4; mt++)
#pragma unroll
        for (int half = 0; half < 2; half++) {
            float v = sloc[mt][half];
            v += __shfl_xor_sync(0xFFFFFFFFu, v, 1);
            v += __shfl_xor_sync(0xFFFFFFFFu, v, 2);
            if ((lane & 3) == 0) {
                int row = m0 + m_base + mt * 16 + (lane >> 2) + half * 8;
                rowp[((size_t)bh * LSEQ + row) * 64 + nt_blk * 4 + (wid >> 1)] = v;
            }
        }
    __syncthreads();

    float* ap = attn + ((size_t)bh * LSEQ + m0) * LSEQ + n0;
    for (int i = tid; i < 128 * 128; i += 256) {
        int r = i >> 7, c = i & 127;
        ap[(size_t)r * LSEQ + c] = E[r * 130 + c];
    }
}

__global__ void rowsum_kernel(const float* __restrict__ rowp, float* __restrict__ rinv) {
    int i = blockIdx.x * blockDim.x + threadIdx.x;
    if (i < NBH * LSEQ) {
        float s = 0.f;
#pragma unroll
        for (int j = 0; j < 64; j++) s += rowp[(size_t)i * 64 + j];
        rinv[i] = 1.0f / s;
    }
}

// ===========================================================================
// Stage C: normalize attn in place + O = P@V, E register double-buffer +
// cp.async V. grid (16, 64), 256 thr, warp tile 32x32 (4x2 grid).
// ===========================================================================
__global__ void __launch_bounds__(256) pv_kernel(
    float* __restrict__ attn,
    const __nv_bfloat16* __restrict__ vh, const __nv_bfloat16* __restrict__ vl,
    const float* __restrict__ rinv, float* __restrict__ out)
{
    extern __shared__ char smem[];
    const uint32_t sb = smem_u32(smem);
    const int tid = threadIdx.x, wid = tid >> 5, lane = tid & 31;
    const int mt_blk = blockIdx.x, bh = blockIdx.y;
    const int m0 = mt_blk * 128;
    const int m_base = (wid & 3) * 32, n_base = (wid >> 2) * 32;

    float* srinv = reinterpret_cast<float*>(smem + V_RINV);
    if (tid < 128) srinv[tid] = rinv[(size_t)bh * LSEQ + m0 + tid];

    float* apb = attn + ((size_t)bh * LSEQ + m0) * LSEQ;
    const __nv_bfloat16* vhb = vh + (size_t)bh * LSEQ * DH;
    const __nv_bfloat16* vlb = vl + (size_t)bh * LSEQ * DH;

    // per-thread E mapping: i = tid + j*256 -> r = i>>4, c4 = (i&15)*4
    const int er = tid >> 4, ec = (tid & 15) * 4;

    float4 Ereg[8];
#pragma unroll
    for (int j = 0; j < 8; j++)
        Ereg[j] = *reinterpret_cast<const float4*>(&apb[(size_t)(er + j * 16) * LSEQ + ec]);

    __syncthreads();   // srinv ready

    float C[2][4][4] = {};

    for (int ck = 0; ck < 32; ck++) {
        const int k0 = ck * 64;
        // async V chunk [64][64]
        for (int i = tid; i < 512; i += 256) {
            int r = i >> 3, c8 = (i & 7) * 8;
            uint32_t d = swz((uint32_t)0, r, c8 * 2);
            size_t ga = (size_t)(k0 + r) * DH + c8;
            cpasync16(sb + V_VH + d, &vhb[ga]);
            cpasync16(sb + V_VL + d, &vlb[ga]);
        }
        CP_COMMIT();

        // normalize current E (in regs), write final attn, split to smem
#pragma unroll
        for (int j = 0; j < 8; j++) {
            int r = er + j * 16;
            float4 e = Ereg[j];
            float ri = srinv[r];
            e.x *= ri; e.y *= ri; e.z *= ri; e.w *= ri;
            *reinterpret_cast<float4*>(&apb[(size_t)r * LSEQ + k0 + ec]) = e;
            uint32_t h0, l0, h1, l1;
            split2(e.x, e.y, h0, l0);
            split2(e.z, e.w, h1, l1);
            uint32_t d = swz((uint32_t)0, r, ec * 2);
            *reinterpret_cast<uint2*>(smem + V_PH + d) = make_uint2(h0, h1);
            *reinterpret_cast<uint2*>(smem + V_PL + d) = make_uint2(l0, l1);
        }
        CP_WAIT(0);
        __syncthreads();

        // prefetch next E chunk into regs (consumed next iteration, hidden by MMA)
        if (ck + 1 < 32) {
#pragma unroll
            for (int j = 0; j < 8; j++)
                Ereg[j] = *reinterpret_cast<const float4*>(
                    &apb[(size_t)(er + j * 16) * LSEQ + (k0 + 64) + ec]);
        }

#pragma unroll
        for (int term = 0; term < 3; term++) {
            uint32_t As = sb + ((term == 2) ? V_PL : V_PH);
            uint32_t Bs = sb + ((term == 1) ? V_VL : V_VH);
#pragma unroll
            for (int ks = 0; ks < 4; ks++) {
                uint32_t a[2][4];
#pragma unroll
                for (int mt = 0; mt < 2; mt++)
                    ldsm4(a[mt], swz(As, m_base + mt * 16 + (lane & 15), ks * 32 + (lane >> 4) * 16));
                uint32_t b[4][2];
                const int mg = lane >> 3, rs = lane & 7;
#pragma unroll
                for (int p = 0; p < 2; p++) {
                    uint32_t r4[4];
                    int row = ks * 16 + (mg & 1) * 8 + rs;
                    int cb = (n_base + p * 16 + ((mg >= 2) ? 8 : 0)) * 2;
                    ldsm4t(r4, swz(Bs, row, cb));
                    b[2 * p][0] = r4[0]; b[2 * p][1] = r4[1];
                    b[2 * p + 1][0] = r4[2]; b[2 * p + 1][1] = r4[3];
                }
#pragma unroll
                for (int mt = 0; mt < 2; mt++)
#pragma unroll
                    for (int nt = 0; nt < 4; nt++)
                        mma16816(C[mt][nt], a[mt], b[nt]);
            }
        }
        __syncthreads();
    }

    const int b = bh >> 4, h = bh & 15;
#pragma unroll
    for (int mt = 0; mt < 2; mt++)
#pragma unroll
        for (int nt = 0; nt < 4; nt++) {
            int n = n_base + nt * 8 + 2 * (lane & 3);
#pragma unroll
            for (int half = 0; half < 2; half++) {
                int m = m0 + m_base + mt * 16 + (lane >> 2) + half * 8;
                *reinterpret_cast<float2*>(&out[((size_t)b * LSEQ + m) * DM + h * DH + n]) =
                    make_float2(C[mt][nt][half * 2], C[mt][nt][half * 2 + 1]);
            }
        }
}

// ===========================================================================
extern "C" void kernel_launch(void* const* d_in, const int* in_sizes, int n_in,
                              void* d_out, int out_size) {
    const float* q_in = (const float*)d_in[0];
    const float* k_in = (const float*)d_in[1];
    const float* v_in = (const float*)d_in[2];
    const float* wq   = (const float*)d_in[3];
    const float* wk   = (const float*)d_in[4];
    const float* wv   = (const float*)d_in[5];

    __nv_bfloat16 *xh, *xl, *wh, *wl, *qh, *ql, *kh, *kl, *vh, *vl;
    float *rowp, *rinv, *attn_scratch, *out_scratch;
    cudaGetSymbolAddress((void**)&xh, g_xh);
    cudaGetSymbolAddress((void**)&xl, g_xl);
    cudaGetSymbolAddress((void**)&wh, g_wh);
    cudaGetSymbolAddress((void**)&wl, g_wl);
    cudaGetSymbolAddress((void**)&qh, g_qh);
    cudaGetSymbolAddress((void**)&ql, g_ql);
    cudaGetSymbolAddress((void**)&kh, g_kh);
    cudaGetSymbolAddress((void**)&kl, g_kl);
    cudaGetSymbolAddress((void**)&vh, g_vh);
    cudaGetSymbolAddress((void**)&vl, g_vl);
    cudaGetSymbolAddress((void**)&rowp, g_rowp);
    cudaGetSymbolAddress((void**)&rinv, g_rinv);
    cudaGetSymbolAddress((void**)&attn_scratch, g_attn_s);
    cudaGetSymbolAddress((void**)&out_scratch, g_outs);

    const long long out_elems  = (long long)BSZ * LSEQ * DM;
    const long long attn_elems = (long long)NBH * LSEQ * LSEQ;

    float* out_ptr  = (float*)d_out;
    float* attn_ptr = attn_scratch;
    long long osz = (long long)out_size;
    if (osz >= out_elems + attn_elems) {
        attn_ptr = (float*)d_out + out_elems;
    } else if (osz == attn_elems) {
        attn_ptr = (float*)d_out;
        out_ptr  = out_scratch;
    }

    cudaFuncSetAttribute(proj_kernel,  cudaFuncAttributeMaxDynamicSharedMemorySize, SMEM_PROJ);
    cudaFuncSetAttribute(score_kernel, cudaFuncAttributeMaxDynamicSharedMemorySize, SMEM_SCORE);
    cudaFuncSetAttribute(pv_kernel,    cudaFuncAttributeMaxDynamicSharedMemorySize, SMEM_PV);

    const int xn4 = (BSZ * LSEQ * DM) / 4;
    const int wn4 = (DM * DM) / 4;
    dim3 pgrid(DM / 128, (BSZ * LSEQ) / 128);

    convert_kernel<<<(xn4 + 255) / 256, 256>>>(q_in, xh, xl, xn4);
    convert_kernel<<<(wn4 + 255) / 256, 256>>>(wq, wh, wl, wn4);
    proj_kernel<<<pgrid, 256, SMEM_PROJ>>>(xh, xl, wh, wl, qh, ql);

    convert_kernel<<<(xn4 + 255) / 256, 256>>>(k_in, xh, xl, xn4);
    convert_kernel<<<(wn4 + 255) / 256, 256>>>(wk, wh, wl, wn4);
    proj_kernel<<<pgrid, 256, SMEM_PROJ>>>(xh, xl, wh, wl, kh, kl);

    convert_kernel<<<(xn4 + 255) / 256, 256>>>(v_in, xh, xl, xn4);
    convert_kernel<<<(wn4 + 255) / 256, 256>>>(wv, wh, wl, wn4);
    proj_kernel<<<pgrid, 256, SMEM_PROJ>>>(xh, xl, wh, wl, vh, vl);

    score_kernel<<<dim3(16, 16, NBH), 256, SMEM_SCORE>>>(qh, ql, kh, kl, attn_ptr, rowp);
    rowsum_kernel<<<(NBH * LSEQ + 255) / 256, 256>>>(rowp, rinv);
    pv_kernel<<<dim3(16, NBH), 256, SMEM_PV>>>(attn_ptr, vh, vl, rinv, out_ptr);
}

// round 11
// speedup vs baseline: 2.6829x; 1.4947x over previous
#include <cuda_runtime.h>
#include <cuda_bf16.h>
#include <cstdint>
#include <math.h>

#define BSZ 4
#define HN 16
#define LSEQ 2048
#define DM 1024
#define DH 64
#define NBH (BSZ*HN)
#define XSZ ((size_t)BSZ*LSEQ*DM)
#define WSZ ((size_t)DM*DM)

// ---------------- device scratch ----------------
__device__ __nv_bfloat16 g_xh[3*XSZ];
__device__ __nv_bfloat16 g_xl[3*XSZ];
__device__ __nv_bfloat16 g_wh[3*WSZ];
__device__ __nv_bfloat16 g_wl[3*WSZ];
__device__ __nv_bfloat16 g_qh[(size_t)NBH*LSEQ*DH];
__device__ __nv_bfloat16 g_ql[(size_t)NBH*LSEQ*DH];
__device__ __nv_bfloat16 g_kh[(size_t)NBH*LSEQ*DH];
__device__ __nv_bfloat16 g_kl[(size_t)NBH*LSEQ*DH];
__device__ __nv_bfloat16 g_vh[(size_t)NBH*LSEQ*DH];
__device__ __nv_bfloat16 g_vl[(size_t)NBH*LSEQ*DH];
__device__ float g_rowp[(size_t)NBH*LSEQ*64];
__device__ float g_attn_s[(size_t)NBH*LSEQ*LSEQ];
__device__ float g_outs[(size_t)BSZ*LSEQ*DM];

// ---------------- smem offsets ----------------
// proj: two pipeline stages of 4 tiles [128][64] bf16
#define P_AH 0
#define P_AL 16384
#define P_BH 32768
#define P_BL 49152
#define PSTAGE 65536
#define SMEM_PROJ 131072

#define SMEM_SCORE 66560         // 4 tiles + E staging reuse (128*130*4)

// pv: P tiles + 2-stage V double buffer + rinv
#define V_PH 0
#define V_PL 16384
#define V_VH0 32768
#define V_VL0 40960
#define V_VH1 49152
#define V_VL1 57344
#define V_RINV 65536
#define SMEM_PV 66048

// ---------------- async copy helpers ----------------
__device__ __forceinline__ void cpasync16(uint32_t saddr, const void* g) {
    asm volatile("cp.async.cg.shared.global [%0], [%1], 16;" :: "r"(saddr), "l"(g));
}
#define CP_COMMIT()  asm volatile("cp.async.commit_group;")
#define CP_WAIT(N)   asm volatile("cp.async.wait_group %0;" :: "n"(N))

// ---------------- warp mma helpers ----------------
__device__ __forceinline__ uint32_t smem_u32(const void* p) {
    uint32_t a;
    asm("{ .reg .u64 t; cvta.to.shared.u64 t, %1; cvt.u32.u64 %0, t; }" : "=r"(a) : "l"(p));
    return a;
}
__device__ __forceinline__ uint32_t swz(uint32_t base, int r, int cb) {
    uint32_t off = (uint32_t)(r * 128 + cb);
    return base + (off ^ ((off >> 3) & 0x70));
}
__device__ __forceinline__ void ldsm4(uint32_t* r, uint32_t a) {
    asm volatile("ldmatrix.sync.aligned.m8n8.x4.shared.b16 {%0,%1,%2,%3}, [%4];"
        : "=r"(r[0]), "=r"(r[1]), "=r"(r[2]), "=r"(r[3]) : "r"(a));
}
__device__ __forceinline__ void ldsm4t(uint32_t* r, uint32_t a) {
    asm volatile("ldmatrix.sync.aligned.m8n8.x4.trans.shared.b16 {%0,%1,%2,%3}, [%4];"
        : "=r"(r[0]), "=r"(r[1]), "=r"(r[2]), "=r"(r[3]) : "r"(a));
}
__device__ __forceinline__ void mma16816(float* c, const uint32_t* a, const uint32_t* b) {
    asm volatile("mma.sync.aligned.m16n8k16.row.col.f32.bf16.bf16.f32 "
        "{%0,%1,%2,%3}, {%4,%5,%6,%7}, {%8,%9}, {%0,%1,%2,%3};"
        : "+f"(c[0]), "+f"(c[1]), "+f"(c[2]), "+f"(c[3])
        : "r"(a[0]), "r"(a[1]), "r"(a[2]), "r"(a[3]), "r"(b[0]), "r"(b[1]));
}

// ---------------- math helpers ----------------
__device__ __forceinline__ void split2(float a, float b, uint32_t& hp, uint32_t& lp) {
    __nv_bfloat16 ah = __float2bfloat16(a), bh = __float2bfloat16(b);
    float al = a - __bfloat162float(ah);
    float bl = b - __bfloat162float(bh);
    __nv_bfloat162 hv; hv.x = ah; hv.y = bh;
    __nv_bfloat162 lv; lv.x = __float2bfloat16(al); lv.y = __float2bfloat16(bl);
    hp = *reinterpret_cast<uint32_t*>(&hv);
    lp = *reinterpret_cast<uint32_t*>(&lv);
}
__device__ __forceinline__ float fast_exp8(float raw) {
    float y = raw * 0.180336880090206f;          // (1/8)*log2(e)
    int n = __float2int_rn(y);
    float f = y - (float)n;
    float p = 1.54035304e-4f;
    p = fmaf(p, f, 1.33335581e-3f);
    p = fmaf(p, f, 9.61812911e-3f);
    p = fmaf(p, f, 5.55041087e-2f);
    p = fmaf(p, f, 2.40226507e-1f);
    p = fmaf(p, f, 6.93147181e-1f);
    p = fmaf(p, f, 1.0f);
    return p * __int_as_float((n + 127) << 23);
}

// ===========================================================================
// convert_all: 6 tensors in one launch. grid.y: 0-2 = X (q,k,v), 3-5 = W.
// ===========================================================================
__global__ void convert_all_kernel(
    const float* __restrict__ s0, const float* __restrict__ s1, const float* __restrict__ s2,
    const float* __restrict__ s3, const float* __restrict__ s4, const float* __restrict__ s5,
    __nv_bfloat16* __restrict__ xh, __nv_bfloat16* __restrict__ xl,
    __nv_bfloat16* __restrict__ wh, __nv_bfloat16* __restrict__ wl)
{
    const int y = blockIdx.y;
    const float* srcs[6] = {s0, s1, s2, s3, s4, s5};
    const float* src = srcs[y];
    __nv_bfloat16 *hi, *lo;
    int n4;
    if (y < 3) { hi = xh + (size_t)y * XSZ; lo = xl + (size_t)y * XSZ; n4 = (int)(XSZ / 4); }
    else       { hi = wh + (size_t)(y - 3) * WSZ; lo = wl + (size_t)(y - 3) * WSZ; n4 = (int)(WSZ / 4); }
    int i = blockIdx.x * blockDim.x + threadIdx.x;
    if (i < n4) {
        float4 v = reinterpret_cast<const float4*>(src)[i];
        uint32_t h0, l0, h1, l1;
        split2(v.x, v.y, h0, l0);
        split2(v.z, v.w, h1, l1);
        reinterpret_cast<uint2*>(hi)[i] = make_uint2(h0, h1);
        reinterpret_cast<uint2*>(lo)[i] = make_uint2(l0, l1);
    }
}

// ===========================================================================
// Warp-tile MMA core: 64x32 warp tile, K-chunk 64, 3 hi/lo terms.
// ===========================================================================
__device__ __forceinline__ void mma_block_64(
    float C[4][4][4], uint32_t ah, uint32_t al, uint32_t bh, uint32_t bl,
    int m_base, int n_base, int lane)
{
#pragma unroll
    for (int term = 0; term < 3; term++) {
        uint32_t As = (term == 2) ? al : ah;
        uint32_t Bs = (term == 1) ? bl : bh;
#pragma unroll
        for (int ks = 0; ks < 4; ks++) {
            uint32_t a[4][4];
#pragma unroll
            for (int mt = 0; mt < 4; mt++)
                ldsm4(a[mt], swz(As, m_base + mt * 16 + (lane & 15), ks * 32 + (lane >> 4) * 16));
            uint32_t b[4][2];
            const int mg = lane >> 3, rs = lane & 7;
#pragma unroll
            for (int p = 0; p < 2; p++) {
                uint32_t r4[4];
                int row = n_base + p * 16 + ((mg >= 2) ? 8 : 0) + rs;
                int cb = ks * 32 + (mg & 1) * 16;
                ldsm4(r4, swz(Bs, row, cb));
                b[2 * p][0] = r4[0]; b[2 * p][1] = r4[1];
                b[2 * p + 1][0] = r4[2]; b[2 * p + 1][1] = r4[3];
            }
#pragma unroll
            for (int mt = 0; mt < 4; mt++)
#pragma unroll
                for (int nt = 0; nt < 4; nt++)
                    mma16816(C[mt][nt], a[mt], b[nt]);
        }
    }
}

// ===========================================================================
// Stage A: all 3 projections in one launch. grid (8, 64, 3), 256 thr.
// Y = X @ W^T, 2-stage cp.async pipeline over 16 K-chunks.
// ===========================================================================
__global__ void __launch_bounds__(256) proj_kernel(
    const __nv_bfloat16* __restrict__ xh_all, const __nv_bfloat16* __restrict__ xl_all,
    const __nv_bfloat16* __restrict__ wh_all, const __nv_bfloat16* __restrict__ wl_all,
    __nv_bfloat16* __restrict__ qh, __nv_bfloat16* __restrict__ ql,
    __nv_bfloat16* __restrict__ kh, __nv_bfloat16* __restrict__ kl,
    __nv_bfloat16* __restrict__ vh, __nv_bfloat16* __restrict__ vl)
{
    extern __shared__ char smem[];
    const uint32_t sb = smem_u32(smem);
    const int tid = threadIdx.x, wid = tid >> 5, lane = tid & 31;
    const int n0 = blockIdx.x * 128, m0 = blockIdx.y * 128;
    const int z = blockIdx.z;
    const int m_base = (wid & 1) * 64, n_base = (wid >> 1) * 32;

    const __nv_bfloat16* xh = xh_all + (size_t)z * XSZ;
    const __nv_bfloat16* xl = xl_all + (size_t)z * XSZ;
    const __nv_bfloat16* wh = wh_all + (size_t)z * WSZ;
    const __nv_bfloat16* wl = wl_all + (size_t)z * WSZ;
    __nv_bfloat16* oh = (z == 0) ? qh : (z == 1) ? kh : vh;
    __nv_bfloat16* ol = (z == 0) ? ql : (z == 1) ? kl : vl;

    auto load_chunk = [&](int ck, int stage) {
        const int k0 = ck * 64;
        const uint32_t st = sb + stage * PSTAGE;
        for (int i = tid; i < 1024; i += 256) {
            int r = i >> 3, c8 = (i & 7) * 8;
            uint32_t d = swz((uint32_t)0, r, c8 * 2);
            size_t ga = (size_t)(m0 + r) * DM + k0 + c8;
            size_t gb = (size_t)(n0 + r) * DM + k0 + c8;
            cpasync16(st + P_AH + d, &xh[ga]);
            cpasync16(st + P_AL + d, &xl[ga]);
            cpasync16(st + P_BH + d, &wh[gb]);
            cpasync16(st + P_BL + d, &wl[gb]);
        }
        CP_COMMIT();
    };

    float C[4][4][4] = {};
    load_chunk(0, 0);
    for (int ck = 0; ck < 16; ck++) {
        const int stage = ck & 1;
        if (ck + 1 < 16) { load_chunk(ck + 1, (ck + 1) & 1); CP_WAIT(1); }
        else             { CP_WAIT(0); }
        __syncthreads();
        const uint32_t st = sb + stage * PSTAGE;
        mma_block_64(C, st + P_AH, st + P_AL, st + P_BH, st + P_BL, m_base, n_base, lane);
        __syncthreads();
    }

#pragma unroll
    for (int mt = 0; mt < 4; mt++) {
#pragma unroll
        for (int nt = 0; nt < 4; nt++) {
            int n = n0 + n_base + nt * 8 + 2 * (lane & 3);
            int h = n >> 6, dd = n & 63;
#pragma unroll
            for (int half = 0; half < 2; half++) {
                int m = m0 + m_base + mt * 16 + (lane >> 2) + half * 8;
                int b = m >> 11, l = m & (LSEQ - 1);
                uint32_t hp, lp;
                split2(C[mt][nt][half * 2], C[mt][nt][half * 2 + 1], hp, lp);
                size_t base = (((size_t)(b * HN + h)) * LSEQ + l) * DH + dd;
                *reinterpret_cast<uint32_t*>(&oh[base]) = hp;
                *reinterpret_cast<uint32_t*>(&ol[base]) = lp;
            }
        }
    }
}

// ===========================================================================
// Stage B: E = exp(QK^T/8) + per-warp row partials.
// ===========================================================================
__global__ void __launch_bounds__(256) score_kernel(
    const __nv_bfloat16* __restrict__ qh, const __nv_bfloat16* __restrict__ ql,
    const __nv_bfloat16* __restrict__ kh, const __nv_bfloat16* __restrict__ kl,
    float* __restrict__ attn, float* __restrict__ rowp)
{
    extern __shared__ char smem[];
    const uint32_t sb = smem_u32(smem);
    const int tid = threadIdx.x, wid = tid >> 5, lane = tid & 31;
    const int nt_blk = blockIdx.x, mt_blk = blockIdx.y, bh = blockIdx.z;
    const int n0 = nt_blk * 128, m0 = mt_blk * 128;
    const int m_base = (wid & 1) * 64, n_base = (wid >> 1) * 32;

    {
        const __nv_bfloat16* sp[4] = {
            qh + ((size_t)bh * LSEQ + m0) * DH, ql + ((size_t)bh * LSEQ + m0) * DH,
            kh + ((size_t)bh * LSEQ + n0) * DH, kl + ((size_t)bh * LSEQ + n0) * DH };
        const int so[4] = {0, 16384, 32768, 49152};
#pragma unroll
        for (int a = 0; a < 4; a++)
            for (int i = tid; i < 1024; i += 256) {
                int r = i >> 3, c8 = (i & 7) * 8;
                uint32_t d = swz((uint32_t)0, r, c8 * 2);
                cpasync16(sb + so[a] + d, &sp[a][(size_t)r * DH + c8]);
            }
        CP_COMMIT(); CP_WAIT(0);
    }
    __syncthreads();

    float C[4][4][4] = {};
    mma_block_64(C, sb + 0, sb + 16384, sb + 32768, sb + 49152, m_base, n_base, lane);
    __syncthreads();   // tiles dead; smem becomes E staging [128][130] f32

    float* E = reinterpret_cast<float*>(smem);
    float sloc[4][2] = {};
#pragma unroll
    for (int mt = 0; mt < 4; mt++)
#pragma unroll
        for (int nt = 0; nt < 4; nt++)
#pragma unroll
            for (int half = 0; half < 2; half++) {
                float e0 = fast_exp8(C[mt][nt][half * 2]);
                float e1 = fast_exp8(C[mt][nt][half * 2 + 1]);
                sloc[mt][half] += e0 + e1;
                int row = m_base + mt * 16 + (lane >> 2) + half * 8;
                int col = n_base + nt * 8 + 2 * (lane & 3);
                *reinterpret_cast<float2*>(&E[row * 130 + col]) = make_float2(e0, e1);
            }

#pragma unroll
    for (int mt = 0; mt < 4; mt++)
#pragma unroll
        for (int half = 0; half < 2; half++) {
            float v = sloc[mt][half];
            v += __shfl_xor_sync(0xFFFFFFFFu, v, 1);
            v += __shfl_xor_sync(0xFFFFFFFFu, v, 2);
            if ((lane & 3) == 0) {
                int row = m0 + m_base + mt * 16 + (lane >> 2) + half * 8;
                rowp[((size_t)bh * LSEQ + row) * 64 + nt_blk * 4 + (wid >> 1)] = v;
            }
        }
    __syncthreads();

    float* ap = attn + ((size_t)bh * LSEQ + m0) * LSEQ + n0;
    for (int i = tid; i < 128 * 128; i += 256) {
        int r = i >> 7, c = i & 127;
        ap[(size_t)r * LSEQ + c] = E[r * 130 + c];
    }
}

// ===========================================================================
// Stage C: rowsum (prologue) + normalize attn in place + O = P@V.
// E register double-buffer + 2-stage cp.async V. grid (16, 64), 256 thr.
// ===========================================================================
__global__ void __launch_bounds__(256) pv_kernel(
    float* __restrict__ attn, const float* __restrict__ rowp,
    const __nv_bfloat16* __restrict__ vh, const __nv_bfloat16* __restrict__ vl,
    float* __restrict__ out)
{
    extern __shared__ char smem[];
    const uint32_t sb = smem_u32(smem);
    const int tid = threadIdx.x, wid = tid >> 5, lane = tid & 31;
    const int mt_blk = blockIdx.x, bh = blockIdx.y;
    const int m0 = mt_blk * 128;
    const int m_base = (wid & 3) * 32, n_base = (wid >> 2) * 32;

    // rowsum reduce for this block's 128 rows (deterministic fixed order)
    float* srinv = reinterpret_cast<float*>(smem + V_RINV);
    if (tid < 128) {
        const float* rp = &rowp[((size_t)bh * LSEQ + m0 + tid) * 64];
        float s = 0.f;
#pragma unroll
        for (int j = 0; j < 64; j++) s += rp[j];
        srinv[tid] = 1.0f / s;
    }

    float* apb = attn + ((size_t)bh * LSEQ + m0) * LSEQ;
    const __nv_bfloat16* vhb = vh + (size_t)bh * LSEQ * DH;
    const __nv_bfloat16* vlb = vl + (size_t)bh * LSEQ * DH;

    const int er = tid >> 4, ec = (tid & 15) * 4;

    auto load_v = [&](int ck, int stage) {
        const int k0 = ck * 64;
        const uint32_t vH = sb + (stage ? V_VH1 : V_VH0);
        const uint32_t vL = sb + (stage ? V_VL1 : V_VL0);
        for (int i = tid; i < 512; i += 256) {
            int r = i >> 3, c8 = (i & 7) * 8;
            uint32_t d = swz((uint32_t)0, r, c8 * 2);
            size_t ga = (size_t)(k0 + r) * DH + c8;
            cpasync16(vH + d, &vhb[ga]);
            cpasync16(vL + d, &vlb[ga]);
        }
        CP_COMMIT();
    };

    float4 Ereg[8];
#pragma unroll
    for (int j = 0; j < 8; j++)
        Ereg[j] = *reinterpret_cast<const float4*>(&apb[(size_t)(er + j * 16) * LSEQ + ec]);

    load_v(0, 0);
    __syncthreads();   // srinv ready

    float C[2][4][4] = {};

    for (int ck = 0; ck < 32; ck++) {
        const int k0 = ck * 64;
        const int stage = ck & 1;
        if (ck + 1 < 32) load_v(ck + 1, stage ^ 1);

        // normalize current E (in regs), write final attn, split to smem
#pragma unroll
        for (int j = 0; j < 8; j++) {
            int r = er + j * 16;
            float4 e = Ereg[j];
            float ri = srinv[r];
            e.x *= ri; e.y *= ri; e.z *= ri; e.w *= ri;
            *reinterpret_cast<float4*>(&apb[(size_t)r * LSEQ + k0 + ec]) = e;
            uint32_t h0, l0, h1, l1;
            split2(e.x, e.y, h0, l0);
            split2(e.z, e.w, h1, l1);
            uint32_t d = swz((uint32_t)0, r, ec * 2);
            *reinterpret_cast<uint2*>(smem + V_PH + d) = make_uint2(h0, h1);
            *reinterpret_cast<uint2*>(smem + V_PL + d) = make_uint2(l0, l1);
        }
        if (ck + 1 < 32) { CP_WAIT(1); } else { CP_WAIT(0); }
        __syncthreads();

        // prefetch next E chunk into regs (hidden by MMA)
        if (ck + 1 < 32) {
#pragma unroll
            for (int j = 0; j < 8; j++)
                Ereg[j] = *reinterpret_cast<const float4*>(
                    &apb[(size_t)(er + j * 16) * LSEQ + (k0 + 64) + ec]);
        }

        const uint32_t vH = sb + (stage ? V_VH1 : V_VH0);
        const uint32_t vL = sb + (stage ? V_VL1 : V_VL0);
#pragma unroll
        for (int term = 0; term < 3; term++) {
            uint32_t As = sb + ((term == 2) ? V_PL : V_PH);
            uint32_t Bs = (term == 1) ? vL : vH;
#pragma unroll
            for (int ks = 0; ks < 4; ks++) {
                uint32_t a[2][4];
#pragma unroll
                for (int mt = 0; mt < 2; mt++)
                    ldsm4(a[mt], swz(As, m_base + mt * 16 + (lane & 15), ks * 32 + (lane >> 4) * 16));
                uint32_t b[4][2];
                const int mg = lane >> 3, rs = lane & 7;
#pragma unroll
                for (int p = 0; p < 2; p++) {
                    uint32_t r4[4];
                    int row = ks * 16 + (mg & 1) * 8 + rs;
                    int cb = (n_base + p * 16 + ((mg >= 2) ? 8 : 0)) * 2;
                    ldsm4t(r4, swz(Bs, row, cb));
                    b[2 * p][0] = r4[0]; b[2 * p][1] = r4[1];
                    b[2 * p + 1][0] = r4[2]; b[2 * p + 1][1] = r4[3];
                }
#pragma unroll
                for (int mt = 0; mt < 2; mt++)
#pragma unroll
                    for (int nt = 0; nt < 4; nt++)
                        mma16816(C[mt][nt], a[mt], b[nt]);
            }
        }
        __syncthreads();
    }

    const int b = bh >> 4, h = bh & 15;
#pragma unroll
    for (int mt = 0; mt < 2; mt++)
#pragma unroll
        for (int nt = 0; nt < 4; nt++) {
            int n = n_base + nt * 8 + 2 * (lane & 3);
#pragma unroll
            for (int half = 0; half < 2; half++) {
                int m = m0 + m_base + mt * 16 + (lane >> 2) + half * 8;
                *reinterpret_cast<float2*>(&out[((size_t)b * LSEQ + m) * DM + h * DH + n]) =
                    make_float2(C[mt][nt][half * 2], C[mt][nt][half * 2 + 1]);
            }
        }
}

// ===========================================================================
extern "C" void kernel_launch(void* const* d_in, const int* in_sizes, int n_in,
                              void* d_out, int out_size) {
    const float* q_in = (const float*)d_in[0];
    const float* k_in = (const float*)d_in[1];
    const float* v_in = (const float*)d_in[2];
    const float* wq   = (const float*)d_in[3];
    const float* wk   = (const float*)d_in[4];
    const float* wv   = (const float*)d_in[5];

    __nv_bfloat16 *xh, *xl, *wh, *wl, *qh, *ql, *kh, *kl, *vh, *vl;
    float *rowp, *attn_scratch, *out_scratch;
    cudaGetSymbolAddress((void**)&xh, g_xh);
    cudaGetSymbolAddress((void**)&xl, g_xl);
    cudaGetSymbolAddress((void**)&wh, g_wh);
    cudaGetSymbolAddress((void**)&wl, g_wl);
    cudaGetSymbolAddress((void**)&qh, g_qh);
    cudaGetSymbolAddress((void**)&ql, g_ql);
    cudaGetSymbolAddress((void**)&kh, g_kh);
    cudaGetSymbolAddress((void**)&kl, g_kl);
    cudaGetSymbolAddress((void**)&vh, g_vh);
    cudaGetSymbolAddress((void**)&vl, g_vl);
    cudaGetSymbolAddress((void**)&rowp, g_rowp);
    cudaGetSymbolAddress((void**)&attn_scratch, g_attn_s);
    cudaGetSymbolAddress((void**)&out_scratch, g_outs);

    const long long out_elems  = (long long)BSZ * LSEQ * DM;
    const long long attn_elems = (long long)NBH * LSEQ * LSEQ;

    float* out_ptr  = (float*)d_out;
    float* attn_ptr = attn_scratch;
    long long osz = (long long)out_size;
    if (osz >= out_elems + attn_elems) {
        attn_ptr = (float*)d_out + out_elems;
    } else if (osz == attn_elems) {
        attn_ptr = (float*)d_out;
        out_ptr  = out_scratch;
    }

    cudaFuncSetAttribute(proj_kernel,  cudaFuncAttributeMaxDynamicSharedMemorySize, SMEM_PROJ);
    cudaFuncSetAttribute(score_kernel, cudaFuncAttributeMaxDynamicSharedMemorySize, SMEM_SCORE);
    cudaFuncSetAttribute(pv_kernel,    cudaFuncAttributeMaxDynamicSharedMemorySize, SMEM_PV);

    const int xblocks = (int)((XSZ / 4 + 255) / 256);
    convert_all_kernel<<<dim3(xblocks, 6), 256>>>(
        q_in, k_in, v_in, wq, wk, wv, xh, xl, wh, wl);

    proj_kernel<<<dim3(DM / 128, (BSZ * LSEQ) / 128, 3), 256, SMEM_PROJ>>>(
        xh, xl, wh, wl, qh, ql, kh, kl, vh, vl);

    score_kernel<<<dim3(16, 16, NBH), 256, SMEM_SCORE>>>(qh, ql, kh, kl, attn_ptr, rowp);
    pv_kernel<<<dim3(16, NBH), 256, SMEM_PV>>>(attn_ptr, rowp, vh, vl, out_ptr);
}